// round 5
// baseline (speedup 1.0000x reference)
#include <cuda_runtime.h>
#include <cuda_bf16.h>
#include <cstdint>

#define TT   32
#define BB   16
#define INS  64
#define OUTS 64
#define LL   4096
#define WW   64
#define CO   332      // OUT + 70 + 198
#define NBLK 128
#define NTHR 512
#define CHUNK 512     // L-columns per CTA
#define CLS  8        // CTAs per cluster (= one batch)

// ---- smem layout (float offsets) ----
#define S_MEM 0          // 64*512 memory slice [w][l]
#define S_SWR 32768      // 512 normalized read w (w_prev)
#define S_SWW 33280      // 512 normalized write w
#define S_ER  33792      // 512 exp read
#define S_EW  34304      // 512 exp write
#define S_WUR 34816      // 512 sharpened unnorm read
#define S_WUW 35328      // 512 sharpened unnorm write
#define S_EA  35840      // 128 keys (ph2) / e|a (ph4)
#define S_SCR 35968      // 512 scratch (ph1 cat/co/scal, staging, reductions)
#define S_PAR 36480      // 288 params (leader)
#define S_SUM 36768      // 8   sums (leader)
#define S_RV  36776      // 64  read vector accum (leader)
#define S_OUT 36840      // 64  controller out (leader)
#define S_COX 36904      // 32*332 = 10624 precomputed x@Wc + bc (leader)
#define S_TOT 47528      // floats -> 190112 bytes

__device__ __forceinline__ float softplusf(float x) {
    return (x > 20.f) ? x : log1pf(__expf(x));
}
__device__ __forceinline__ float sigmoidf(float x) {
    return 1.f / (1.f + __expf(-x));
}
__device__ __forceinline__ uint32_t smem_u32(const void* p) {
    return (uint32_t)__cvta_generic_to_shared(p);
}
__device__ __forceinline__ uint32_t mapa_u32(uint32_t addr, uint32_t rank) {
    uint32_t r;
    asm("mapa.shared::cluster.u32 %0, %1, %2;" : "=r"(r) : "r"(addr), "r"(rank));
    return r;
}
__device__ __forceinline__ float ld_dsmem(uint32_t a) {
    float v; asm volatile("ld.shared::cluster.f32 %0, [%1];" : "=f"(v) : "r"(a)); return v;
}
__device__ __forceinline__ void st_dsmem(uint32_t a, float v) {
    asm volatile("st.shared::cluster.f32 [%0], %1;" :: "r"(a), "f"(v) : "memory");
}
__device__ __forceinline__ void atom_add_dsmem(uint32_t a, float v) {
    float d;
    asm volatile("atom.relaxed.cluster.shared::cluster.add.f32 %0, [%1], %2;"
                 : "=f"(d) : "r"(a), "f"(v) : "memory");
}
#define CLUSTER_SYNC() do { \
    asm volatile("barrier.cluster.arrive.aligned;" ::: "memory"); \
    asm volatile("barrier.cluster.wait.aligned;"   ::: "memory"); \
} while(0)

__global__ __launch_bounds__(NTHR, 1) __cluster_dims__(CLS, 1, 1)
void ntm_kernel(const float* __restrict__ x, const float* __restrict__ Wc,
                const float* __restrict__ bc, float* __restrict__ dout)
{
    extern __shared__ __align__(16) float sh[];
    const int tid  = threadIdx.x;
    const int warp = tid >> 5;
    const int lane = tid & 31;
    uint32_t rank;
    asm("mov.u32 %0, %%cluster_ctarank;" : "=r"(rank));
    const int b  = blockIdx.x / CLS;      // batch
    const int l0 = (int)rank * CHUNK;
    const bool leader = (rank == 0);

    const uint32_t my_base  = smem_u32(sh);
    const uint32_t ld_base  = mapa_u32(my_base, 0);                 // leader
    const uint32_t prv_base = mapa_u32(my_base, (rank + CLS-1) % CLS);
    const uint32_t nxt_base = mapa_u32(my_base, (rank + 1) % CLS);

    // ---------------- init ----------------
    {
        float4* m4 = (float4*)(sh + S_MEM);
        for (int i = tid; i < WW*CHUNK/4; i += NTHR) m4[i] = make_float4(0,0,0,0);
        for (int k = tid; k < CHUNK; k += NTHR) {
            float v = (l0 + k == 0) ? 1.f : 0.f;
            sh[S_SWR + k] = v; sh[S_SWW + k] = v;
        }
        if (leader) {
            if (tid < 64) { sh[S_OUT + tid] = 0.f; sh[S_RV + tid] = 0.f; }
            if (tid < 8)  sh[S_SUM + tid] = 0.f;
        }
        // coX: all 8 CTAs compute disjoint slices, push to leader smem
        const int per = (TT*CO + CLS-1) / CLS;          // 1328
        const int lo = (int)rank*per, hi = min(lo+per, TT*CO);
        for (int idx = lo + tid; idx < hi; idx += NTHR) {
            const int t = idx / CO, j = idx % CO;
            const float* xp = x + (t*BB + b) * INS;
            float acc = bc[j];
            #pragma unroll 8
            for (int i = 0; i < INS; i++) acc = fmaf(xp[i], Wc[i*CO + j], acc);
            st_dsmem(ld_base + (S_COX + idx)*4u, acc);
        }
    }
    CLUSTER_SYNC();

    for (int t = 0; t < TT; ++t) {
        // -------- Phase 1: controller + params (leader only) --------------
        if (leader) {
            float* cat  = sh + S_SCR;          // 128
            float* co   = sh + S_SCR + 128;    // 332
            float* scal = sh + S_SCR + 464;    // 16
            if (tid < 64)       cat[tid] = sh[S_OUT + tid];
            else if (tid < 128) cat[tid] = sh[S_RV + tid - 64];
            __syncthreads();
            if (tid < CO) {
                const float* wbase = Wc + INS*CO;
                float acc = sh[S_COX + t*CO + tid];
                #pragma unroll 16
                for (int i = 0; i < 128; i++)
                    acc = fmaf(cat[i], __ldg(&wbase[i*CO + tid]), acc);
                co[tid] = acc;
            }
            __syncthreads();
            if (warp == 0) {           // ||k_r||^2
                float p = co[64+lane]*co[64+lane] + co[96+lane]*co[96+lane];
                #pragma unroll
                for (int o = 16; o; o >>= 1) p += __shfl_xor_sync(0xffffffffu, p, o);
                if (lane == 0) scal[14] = p;
            } else if (warp == 1) {    // ||k_w||^2
                float p = co[134+lane]*co[134+lane] + co[166+lane]*co[166+lane];
                #pragma unroll
                for (int o = 16; o; o >>= 1) p += __shfl_xor_sync(0xffffffffu, p, o);
                if (lane == 0) scal[15] = p;
            }
            __syncthreads();
            float* P = sh + S_PAR;
            if (tid == 0) {
                float beta_r = softplusf(co[128]);
                float beta_w = softplusf(co[198]);
                scal[0] = beta_r * rsqrtf(scal[14] + 1e-14f);
                scal[1] = beta_w * rsqrtf(scal[15] + 1e-14f);
                P[128] = beta_r;
                P[129] = sigmoidf(co[129]);
                P[130] = softplusf(co[130]) + 1.f;
                float m = fmaxf(co[131], fmaxf(co[132], co[133]));
                float e0=__expf(co[131]-m), e1=__expf(co[132]-m), e2=__expf(co[133]-m);
                float inv = 1.f/(e0+e1+e2);
                P[131]=e0*inv; P[132]=e1*inv; P[133]=e2*inv;
                P[134] = beta_w;
                P[135] = sigmoidf(co[199]);
                P[136] = softplusf(co[200]) + 1.f;
                m = fmaxf(co[201], fmaxf(co[202], co[203]));
                e0=__expf(co[201]-m); e1=__expf(co[202]-m); e2=__expf(co[203]-m);
                inv = 1.f/(e0+e1+e2);
                P[137]=e0*inv; P[138]=e1*inv; P[139]=e2*inv;
            }
            __syncthreads();
            if (tid < 64) {
                P[tid]       = co[64 + tid]  * scal[0];   // k_r * beta/||k_r||
                P[64 + tid]  = co[134 + tid] * scal[1];   // k_w * beta/||k_w||
                P[140 + tid] = sigmoidf(co[204 + tid]);   // e
                P[204 + tid] = co[268 + tid];             // a
                float o = co[tid];
                sh[S_OUT + tid] = o;
                dout[(t*BB + b)*OUTS + tid] = o;          // emit
                sh[S_RV + tid] = 0.f;                     // reset accumulator
            }
            if (tid < 8) sh[S_SUM + tid] = 0.f;
        }
        CLUSTER_SYNC();

        // -------- Phase 2: cosine similarity (smem, reduction-free) -------
        {
            if (tid < 128)       sh[S_EA + tid]  = ld_dsmem(ld_base + (S_PAR + tid)*4u);
            else if (tid == 128) sh[S_SCR + 40] = ld_dsmem(ld_base + (S_PAR + 128)*4u);
            else if (tid == 129) sh[S_SCR + 41] = ld_dsmem(ld_base + (S_PAR + 134)*4u);
            __syncthreads();
            const float beta_r = sh[S_SCR + 40];
            const float beta_w = sh[S_SCR + 41];
            const int l = tid;
            float dr = 0.f, dw = 0.f, ds = 0.f;
            #pragma unroll 16
            for (int w = 0; w < WW; ++w) {
                const float m  = sh[S_MEM + w*CHUNK + l];
                dr = fmaf(m, sh[S_EA + w],      dr);
                dw = fmaf(m, sh[S_EA + 64 + w], dw);
                ds = fmaf(m, m,                 ds);
            }
            const float inm = rsqrtf(ds + 1e-14f);
            const float er = __expf(dr*inm - beta_r);   // arg in [-2b, 0]
            const float ew = __expf(dw*inm - beta_w);
            sh[S_ER + l] = er; sh[S_EW + l] = ew;
            float s_er = er, s_ew = ew;
            #pragma unroll
            for (int o = 16; o; o >>= 1) {
                s_er += __shfl_xor_sync(0xffffffffu, s_er, o);
                s_ew += __shfl_xor_sync(0xffffffffu, s_ew, o);
            }
            if (lane == 0) { sh[S_SCR + warp] = s_er; sh[S_SCR + 16 + warp] = s_ew; }
            __syncthreads();
            if (tid == 0) {
                float a = 0.f, c = 0.f;
                #pragma unroll
                for (int i = 0; i < 16; ++i) { a += sh[S_SCR+i]; c += sh[S_SCR+16+i]; }
                atom_add_dsmem(ld_base + (S_SUM + 0)*4u, a);
                atom_add_dsmem(ld_base + (S_SUM + 1)*4u, c);
            }
        }
        CLUSTER_SYNC();

        // -------- Phase 3: gate + shift + sharpen --------------------------
        {
            // stage scalars from leader: P[128..139] -> SCR[32..43], sums -> [44,45]
            if (tid < 12)       sh[S_SCR + 32 + tid] = ld_dsmem(ld_base + (S_PAR + 128 + tid)*4u);
            else if (tid == 12) sh[S_SCR + 44] = ld_dsmem(ld_base + (S_SUM + 0)*4u);
            else if (tid == 13) sh[S_SCR + 45] = ld_dsmem(ld_base + (S_SUM + 1)*4u);
            __syncthreads();
            const float inv_ser = 1.f / sh[S_SCR + 44];
            const float inv_sew = 1.f / sh[S_SCR + 45];
            const float gr  = sh[S_SCR + 33], gamr = sh[S_SCR + 34];
            const float sr0 = sh[S_SCR + 35], sr1 = sh[S_SCR + 36], sr2 = sh[S_SCR + 37];
            const float gw  = sh[S_SCR + 39], gamw = sh[S_SCR + 40];
            const float sw0 = sh[S_SCR + 41], sw1 = sh[S_SCR + 42], sw2 = sh[S_SCR + 43];
            const int k = tid;
            // halos via DSMEM from neighbor CTAs (wraps inside cluster)
            float cmr, cpr, pmr, ppr, cmw, cpw, pmw, ppw;
            if (k == 0) {
                cmr = ld_dsmem(prv_base + (S_ER  + 511)*4u);
                cmw = ld_dsmem(prv_base + (S_EW  + 511)*4u);
                pmr = ld_dsmem(prv_base + (S_SWR + 511)*4u);
                pmw = ld_dsmem(prv_base + (S_SWW + 511)*4u);
            } else {
                cmr = sh[S_ER + k - 1];  cmw = sh[S_EW + k - 1];
                pmr = sh[S_SWR + k - 1]; pmw = sh[S_SWW + k - 1];
            }
            if (k == CHUNK-1) {
                cpr = ld_dsmem(nxt_base + (S_ER  + 0)*4u);
                cpw = ld_dsmem(nxt_base + (S_EW  + 0)*4u);
                ppr = ld_dsmem(nxt_base + (S_SWR + 0)*4u);
                ppw = ld_dsmem(nxt_base + (S_SWW + 0)*4u);
            } else {
                cpr = sh[S_ER + k + 1];  cpw = sh[S_EW + k + 1];
                ppr = sh[S_SWR + k + 1]; ppw = sh[S_SWW + k + 1];
            }
            const float ccr = sh[S_ER + k],  pcr = sh[S_SWR + k];
            const float ccw = sh[S_EW + k],  pcw = sh[S_SWW + k];
            float wgm = cmr*inv_ser*gr + (1.f-gr)*pmr;
            float wgc = ccr*inv_ser*gr + (1.f-gr)*pcr;
            float wgp = cpr*inv_ser*gr + (1.f-gr)*ppr;
            float wur = powf(fmaxf(sr0*wgm + sr1*wgc + sr2*wgp, 0.f), gamr);
            wgm = cmw*inv_sew*gw + (1.f-gw)*pmw;
            wgc = ccw*inv_sew*gw + (1.f-gw)*pcw;
            wgp = cpw*inv_sew*gw + (1.f-gw)*ppw;
            float wuw = powf(fmaxf(sw0*wgm + sw1*wgc + sw2*wgp, 0.f), gamw);
            float ps_r = wur, ps_w = wuw;
            #pragma unroll
            for (int o = 16; o; o >>= 1) {
                ps_r += __shfl_xor_sync(0xffffffffu, ps_r, o);
                ps_w += __shfl_xor_sync(0xffffffffu, ps_w, o);
            }
            __syncthreads();   // SCR staging consumed; reuse for reduction
            sh[S_WUR + k] = wur;
            sh[S_WUW + k] = wuw;
            if (lane == 0) { sh[S_SCR + warp] = ps_r; sh[S_SCR + 16 + warp] = ps_w; }
            __syncthreads();
            if (tid == 0) {
                float a = 0.f, c = 0.f;
                #pragma unroll
                for (int i = 0; i < 16; ++i) { a += sh[S_SCR+i]; c += sh[S_SCR+16+i]; }
                atom_add_dsmem(ld_base + (S_SUM + 2)*4u, a);
                atom_add_dsmem(ld_base + (S_SUM + 3)*4u, c);
            }
        }
        CLUSTER_SYNC();

        // -------- Phase 4: normalize + read vector + memory update ---------
        {
            if (tid < 128)       sh[S_EA + tid]  = ld_dsmem(ld_base + (S_PAR + 140 + tid)*4u);
            else if (tid == 128) sh[S_SCR + 46] = ld_dsmem(ld_base + (S_SUM + 2)*4u);
            else if (tid == 129) sh[S_SCR + 47] = ld_dsmem(ld_base + (S_SUM + 3)*4u);
            __syncthreads();
            const float inv_sr = 1.f / sh[S_SCR + 46];
            const float inv_sw = 1.f / sh[S_SCR + 47];
            {
                const int k = tid;
                sh[S_SWR + k] = sh[S_WUR + k] * inv_sr;
                sh[S_SWW + k] = sh[S_WUW + k] * inv_sw;
            }
            __syncthreads();
            const float4* wr4 = (const float4*)(sh + S_SWR);
            const float4* ww4 = (const float4*)(sh + S_SWW);
            #pragma unroll
            for (int i = 0; i < 4; ++i) {
                const int w = warp*4 + i;
                const float e = sh[S_EA + w], a = sh[S_EA + 64 + w];
                float4* mp = (float4*)(sh + S_MEM + w*CHUNK);
                float racc = 0.f;
                #pragma unroll
                for (int j = lane; j < CHUNK/4; j += 32) {
                    float4 m = mp[j];
                    float4 r = wr4[j];
                    float4 q = ww4[j];
                    racc += m.x*r.x + m.y*r.y + m.z*r.z + m.w*r.w;   // OLD memory
                    m.x = m.x*(1.f - q.x*e) + q.x*a;
                    m.y = m.y*(1.f - q.y*e) + q.y*a;
                    m.z = m.z*(1.f - q.z*e) + q.z*a;
                    m.w = m.w*(1.f - q.w*e) + q.w*a;
                    mp[j] = m;
                }
                #pragma unroll
                for (int o = 16; o; o >>= 1) racc += __shfl_xor_sync(0xffffffffu, racc, o);
                if (lane == 0) atom_add_dsmem(ld_base + (S_RV + w)*4u, racc);
            }
        }
        CLUSTER_SYNC();
    }
}

extern "C" void kernel_launch(void* const* d_in, const int* in_sizes, int n_in,
                              void* d_out, int out_size) {
    const float* x  = (const float*)d_in[0];   // (T,B,IN) fp32
    const float* Wc = (const float*)d_in[1];   // (192,332) fp32
    const float* bc = (const float*)d_in[2];   // (332,)   fp32
    static bool attr_done = false;
    if (!attr_done) {
        cudaFuncSetAttribute(ntm_kernel, cudaFuncAttributeMaxDynamicSharedMemorySize,
                             S_TOT * sizeof(float));
        attr_done = true;
    }
    ntm_kernel<<<NBLK, NTHR, S_TOT * sizeof(float)>>>(x, Wc, bc, (float*)d_out);
}

// round 6
// speedup vs baseline: 1.8431x; 1.8431x over previous
#include <cuda_runtime.h>
#include <cstdint>

#define TT   32
#define BB   16
#define INS  64
#define OUTS 64
#define LL   4096
#define WW   64
#define CO   332      // OUT + 70 + 198
#define NBLK 128
#define NTHR 512
#define CHUNK 512

// ---- smem layout (float offsets) ----
#define S_MEM 0        // 64*512 memory slice [w][l]
#define S_SWR 32768    // 512 normalized read w (w_prev)
#define S_SWW 33280    // 512 normalized write w
#define S_ER  33792    // 512 exp read   (init: x staging uses ER..WUW 2048)
#define S_EW  34304    // 512 exp write
#define S_WUR 34816    // 512 sharpened unnorm read
#define S_WUW 35328    // 512 sharpened unnorm write
#define S_SCR 35840    // 512 scratch: cat(128)+co(332)+scal(16); reductions; rpart
#define S_PAR 36352    // 288 params (every block, redundant)
#define S_OUT 36640    // 64  controller out (prev step)
#define S_COX 36704    // 32*332 = 10624 precomputed x@Wc + bc (block-local)
#define S_TOT 47328    // floats -> 189312 bytes

// ---------------- persistent device state ----------------
__device__ float g_WcT[CO*192];                   // transposed controller weights
// mailbox values; slot layout:
//  val2: [0]=s_er [1]=s_ew [2]=er0 [3]=er511 [4]=ew0 [5]=ew511
//  val3: [0]=s_wur [1]=s_wuw
//  val4: [0]=wr0 [1]=wr511 [2]=ww0 [3]=ww511  [16..79]=rpart[64]
__device__ __align__(128) float g_val2[BB][8][8];
__device__ __align__(128) float g_val3[BB][8][8];
__device__ __align__(128) float g_val4[BB][8][96];
__device__ __align__(128) unsigned g_tick2[BB][32];
__device__ __align__(128) unsigned g_tick3[BB][32];
__device__ __align__(128) unsigned g_tick4[BB][32];

__device__ __forceinline__ float softplusf(float x) {
    return (x > 20.f) ? x : log1pf(__expf(x));
}
__device__ __forceinline__ float sigmoidf(float x) {
    return 1.f / (1.f + __expf(-x));
}
__device__ __forceinline__ unsigned ldcg_u(const unsigned* p) {
    unsigned v; asm volatile("ld.global.cg.u32 %0, [%1];" : "=r"(v) : "l"(p)); return v;
}
__device__ __forceinline__ float ldcg_f(const float* p) {
    float v; asm volatile("ld.global.cg.f32 %0, [%1];" : "=f"(v) : "l"(p)); return v;
}
__device__ __forceinline__ void stcg_u(unsigned* p, unsigned v) {
    asm volatile("st.global.cg.u32 [%0], %1;" :: "l"(p), "r"(v) : "memory");
}
__device__ __forceinline__ void stcg_f(float* p, float v) {
    asm volatile("st.global.cg.f32 [%0], %1;" :: "l"(p), "f"(v) : "memory");
}
__device__ __forceinline__ void stcg_f4(float* p, float4 v) {
    asm volatile("st.global.cg.v4.f32 [%0], {%1,%2,%3,%4};"
                 :: "l"(p), "f"(v.x), "f"(v.y), "f"(v.z), "f"(v.w) : "memory");
}

// Poll 8 tickets for exact value `want` (warp 0, lanes 0..7), then block-sync.
__device__ __forceinline__ void poll8(const unsigned* ticks, unsigned want, int tid) {
    if (tid < 8) {
        int n = 0;
        while (ldcg_u(&ticks[tid]) != want) { if (++n > 32) __nanosleep(32); }
    }
    __syncthreads();
}

__global__ __launch_bounds__(NTHR)
void ntm_kernel(const float* __restrict__ x, const float* __restrict__ Wc,
                const float* __restrict__ bc, float* __restrict__ dout)
{
    extern __shared__ __align__(16) float sh[];
    const int tid   = threadIdx.x;
    const int warp  = tid >> 5;
    const int lane  = tid & 31;
    const int b     = blockIdx.x >> 3;   // batch
    const int chunk = blockIdx.x & 7;
    const int l0    = chunk * CHUNK;

    // ================= init =================
    {
        float4* m4 = (float4*)(sh + S_MEM);
        for (int i = tid; i < WW*CHUNK/4; i += NTHR) m4[i] = make_float4(0,0,0,0);
        for (int k = tid; k < CHUNK; k += NTHR) {
            float v = (l0 + k == 0) ? 1.f : 0.f;
            sh[S_SWR + k] = v; sh[S_SWW + k] = v;
        }
        if (tid < 64) sh[S_OUT + tid] = 0.f;
        if (tid == 0) stcg_u(&g_tick2[b][chunk], 0u);   // reset for replay safety

        // WcT slice: rows i in [chunk*24, chunk*24+24), coalesced reads
        for (int idx = tid; idx < 24*CO; idx += NTHR) {
            const int i = chunk*24 + idx / CO;
            const int j = idx % CO;
            stcg_f(&g_WcT[j*192 + i], __ldg(&Wc[i*CO + j]));
        }
        __threadfence();
        __syncthreads();
        if (tid == 0) stcg_u(&g_tick3[b][chunk], 0u);   // init marker (also resets)
        poll8(g_tick3[b], 0u, tid);                     // whole group's WcT done

        // stage x for this batch into ER..WUW scratch (2048 floats)
        for (int idx = tid; idx < TT*INS; idx += NTHR) {
            const int t = idx >> 6, i = idx & 63;
            sh[S_ER + idx] = __ldg(&x[(t*BB + b)*INS + i]);
        }
        __syncthreads();
        // coX[t][j] = bc[j] + x[t] @ WcT[j][0:64]
        if (tid < CO) {
            const float4* wp4 = (const float4*)(g_WcT + tid*192);
            const float bj = __ldg(&bc[tid]);
            #pragma unroll
            for (int th = 0; th < 4; th++) {            // 4 groups of 8 timesteps
                float acc[8];
                #pragma unroll
                for (int k = 0; k < 8; k++) acc[k] = bj;
                #pragma unroll 4
                for (int q = 0; q < 16; q++) {
                    const float4 w = __ldg(wp4 + q);
                    #pragma unroll
                    for (int k = 0; k < 8; k++) {
                        const float* xr = sh + S_ER + (th*8 + k)*64 + q*4;
                        acc[k] = fmaf(w.x, xr[0], acc[k]);
                        acc[k] = fmaf(w.y, xr[1], acc[k]);
                        acc[k] = fmaf(w.z, xr[2], acc[k]);
                        acc[k] = fmaf(w.w, xr[3], acc[k]);
                    }
                }
                #pragma unroll
                for (int k = 0; k < 8; k++)
                    sh[S_COX + (th*8 + k)*CO + tid] = acc[k];
            }
        }
        __syncthreads();
        // post initial val4 (halos for initial w, rpart = 0) + tick4 = 0
        if (tid < 16) {
            stcg_f4(&g_val4[b][chunk][16 + 4*tid], make_float4(0,0,0,0));
            __threadfence();
        } else if (tid == 16) {
            const float d0 = (l0 == 0) ? 1.f : 0.f;
            stcg_f4(&g_val4[b][chunk][0], make_float4(d0, 0.f, d0, 0.f));
            __threadfence();
        }
        __syncthreads();
        if (tid == 0) stcg_u(&g_tick4[b][chunk], 0u);
    }

    for (int t = 0; t < TT; ++t) {
        // ===== Phase 1: poll step-start, r-sum, controller GEMM, params =====
        poll8(g_tick4[b], (unsigned)t, tid);
        if (tid < 64) {
            float s = 0.f;
            #pragma unroll
            for (int i = 0; i < 8; i++) s += ldcg_f(&g_val4[b][i][16 + tid]);
            sh[S_SCR + tid]      = sh[S_OUT + tid];   // cat[0:64]  = out_{t-1}
            sh[S_SCR + 64 + tid] = s;                 // cat[64:128] = r_{t-1}
        }
        __syncthreads();
        if (tid < CO) {
            float acc = sh[S_COX + t*CO + tid];
            const float4* wp4  = (const float4*)(g_WcT + tid*192 + 64);
            const float4* cat4 = (const float4*)(sh + S_SCR);
            #pragma unroll 8
            for (int q = 0; q < 32; q++) {
                const float4 w = __ldg(wp4 + q);
                const float4 c = cat4[q];
                acc = fmaf(w.x, c.x, acc); acc = fmaf(w.y, c.y, acc);
                acc = fmaf(w.z, c.z, acc); acc = fmaf(w.w, c.w, acc);
            }
            sh[S_SCR + 128 + tid] = acc;              // co
        }
        __syncthreads();
        float* co   = sh + S_SCR + 128;
        float* scal = sh + S_SCR + 464;
        if (warp == 0) {            // ||k_r||^2
            float p = co[64+lane]*co[64+lane] + co[96+lane]*co[96+lane];
            #pragma unroll
            for (int o = 16; o; o >>= 1) p += __shfl_xor_sync(0xffffffffu, p, o);
            if (lane == 0) scal[14] = p;
        } else if (warp == 1) {     // ||k_w||^2
            float p = co[134+lane]*co[134+lane] + co[166+lane]*co[166+lane];
            #pragma unroll
            for (int o = 16; o; o >>= 1) p += __shfl_xor_sync(0xffffffffu, p, o);
            if (lane == 0) scal[15] = p;
        }
        __syncthreads();
        float* P = sh + S_PAR;
        if (tid == 0) {
            float beta_r = softplusf(co[128]);
            float beta_w = softplusf(co[198]);
            scal[0] = beta_r * rsqrtf(scal[14] + 1e-14f);
            scal[1] = beta_w * rsqrtf(scal[15] + 1e-14f);
            P[128] = beta_r;
            P[129] = sigmoidf(co[129]);
            P[130] = softplusf(co[130]) + 1.f;
            float m = fmaxf(co[131], fmaxf(co[132], co[133]));
            float e0=__expf(co[131]-m), e1=__expf(co[132]-m), e2=__expf(co[133]-m);
            float inv = 1.f/(e0+e1+e2);
            P[131]=e0*inv; P[132]=e1*inv; P[133]=e2*inv;
            P[134] = beta_w;
            P[135] = sigmoidf(co[199]);
            P[136] = softplusf(co[200]) + 1.f;
            m = fmaxf(co[201], fmaxf(co[202], co[203]));
            e0=__expf(co[201]-m); e1=__expf(co[202]-m); e2=__expf(co[203]-m);
            inv = 1.f/(e0+e1+e2);
            P[137]=e0*inv; P[138]=e1*inv; P[139]=e2*inv;
        }
        __syncthreads();
        if (tid < 64) {
            P[tid]       = co[64 + tid]  * scal[0];   // k_r * beta/||k_r||
            P[64 + tid]  = co[134 + tid] * scal[1];   // k_w * beta/||k_w||
            P[140 + tid] = sigmoidf(co[204 + tid]);   // e
            P[204 + tid] = co[268 + tid];             // a
            const float o = co[tid];
            sh[S_OUT + tid] = o;
            if (chunk == 0) dout[(t*BB + b)*OUTS + tid] = o;   // emit
        }
        __syncthreads();

        // ===== Phase 2: cosine similarity (smem, reduction-free) =====
        {
            const float beta_r = P[128], beta_w = P[134];
            const int l = tid;
            float dr = 0.f, dw = 0.f, ds = 0.f;
            #pragma unroll 16
            for (int w = 0; w < WW; ++w) {
                const float m = sh[S_MEM + w*CHUNK + l];
                dr = fmaf(m, P[w],      dr);
                dw = fmaf(m, P[64 + w], dw);
                ds = fmaf(m, m,         ds);
            }
            const float inm = rsqrtf(ds + 1e-14f);
            const float er = __expf(dr*inm - beta_r);   // arg in [-2b, 0]
            const float ew = __expf(dw*inm - beta_w);
            sh[S_ER + l] = er; sh[S_EW + l] = ew;
            float se = er, swv = ew;
            #pragma unroll
            for (int o = 16; o; o >>= 1) {
                se  += __shfl_xor_sync(0xffffffffu, se, o);
                swv += __shfl_xor_sync(0xffffffffu, swv, o);
            }
            if (lane == 0) { sh[S_SCR + warp] = se; sh[S_SCR + 16 + warp] = swv; }
            __syncthreads();
            if (tid == 0) {
                float a = 0.f, c = 0.f;
                #pragma unroll
                for (int i = 0; i < 16; ++i) { a += sh[S_SCR+i]; c += sh[S_SCR+16+i]; }
                stcg_f4(&g_val2[b][chunk][0],
                        make_float4(a, c, sh[S_ER+0], sh[S_ER+CHUNK-1]));
                stcg_f4(&g_val2[b][chunk][4],
                        make_float4(sh[S_EW+0], sh[S_EW+CHUNK-1], 0.f, 0.f));
                __threadfence();
                stcg_u(&g_tick2[b][chunk], (unsigned)(t+1));
            }
        }

        // ===== Phase 3: gate + shift + sharpen =====
        poll8(g_tick2[b], (unsigned)(t+1), tid);
        if (tid < 8) {
            float se  = ldcg_f(&g_val2[b][tid][0]);
            float sw2 = ldcg_f(&g_val2[b][tid][1]);
            #pragma unroll
            for (int o = 4; o; o >>= 1) {
                se  += __shfl_xor_sync(0xffu, se,  o, 8);
                sw2 += __shfl_xor_sync(0xffu, sw2, o, 8);
            }
            if (tid == 0) { sh[S_SCR + 40] = se; sh[S_SCR + 41] = sw2; }
        }
        __syncthreads();
        {
            const float inv_ser = 1.f / sh[S_SCR + 40];
            const float inv_sew = 1.f / sh[S_SCR + 41];
            const float gr  = P[129], gamr = P[130];
            const float sr0 = P[131], sr1 = P[132], sr2 = P[133];
            const float gw  = P[135], gamw = P[136];
            const float sw0 = P[137], sw1 = P[138], sw2 = P[139];
            const int prv = (chunk + 7) & 7, nxt = (chunk + 1) & 7;
            const int k = tid;
            float cmr, cmw, pmr, pmw, cpr, cpw, ppr, ppw;
            if (k == 0) {
                cmr = ldcg_f(&g_val2[b][prv][3]); cmw = ldcg_f(&g_val2[b][prv][5]);
                pmr = ldcg_f(&g_val4[b][prv][1]); pmw = ldcg_f(&g_val4[b][prv][3]);
            } else {
                cmr = sh[S_ER + k-1];  cmw = sh[S_EW + k-1];
                pmr = sh[S_SWR + k-1]; pmw = sh[S_SWW + k-1];
            }
            if (k == CHUNK-1) {
                cpr = ldcg_f(&g_val2[b][nxt][2]); cpw = ldcg_f(&g_val2[b][nxt][4]);
                ppr = ldcg_f(&g_val4[b][nxt][0]); ppw = ldcg_f(&g_val4[b][nxt][2]);
            } else {
                cpr = sh[S_ER + k+1];  cpw = sh[S_EW + k+1];
                ppr = sh[S_SWR + k+1]; ppw = sh[S_SWW + k+1];
            }
            const float ccr = sh[S_ER + k],  pcr = sh[S_SWR + k];
            const float ccw = sh[S_EW + k],  pcw = sh[S_SWW + k];
            float wgm = cmr*inv_ser*gr + (1.f-gr)*pmr;
            float wgc = ccr*inv_ser*gr + (1.f-gr)*pcr;
            float wgp = cpr*inv_ser*gr + (1.f-gr)*ppr;
            const float wur = powf(fmaxf(sr0*wgm + sr1*wgc + sr2*wgp, 0.f), gamr);
            wgm = cmw*inv_sew*gw + (1.f-gw)*pmw;
            wgc = ccw*inv_sew*gw + (1.f-gw)*pcw;
            wgp = cpw*inv_sew*gw + (1.f-gw)*ppw;
            const float wuw = powf(fmaxf(sw0*wgm + sw1*wgc + sw2*wgp, 0.f), gamw);
            sh[S_WUR + k] = wur; sh[S_WUW + k] = wuw;
            float ps_r = wur, ps_w = wuw;
            #pragma unroll
            for (int o = 16; o; o >>= 1) {
                ps_r += __shfl_xor_sync(0xffffffffu, ps_r, o);
                ps_w += __shfl_xor_sync(0xffffffffu, ps_w, o);
            }
            if (lane == 0) { sh[S_SCR + warp] = ps_r; sh[S_SCR + 16 + warp] = ps_w; }
            __syncthreads();
            if (tid == 0) {
                float a = 0.f, c = 0.f;
                #pragma unroll
                for (int i = 0; i < 16; ++i) { a += sh[S_SCR+i]; c += sh[S_SCR+16+i]; }
                stcg_f(&g_val3[b][chunk][0], a);
                stcg_f(&g_val3[b][chunk][1], c);
                __threadfence();
                stcg_u(&g_tick3[b][chunk], (unsigned)(t+1));
            }
        }

        // ===== Phase 4: normalize + read vector + memory update =====
        poll8(g_tick3[b], (unsigned)(t+1), tid);
        if (tid < 8) {
            float sr  = ldcg_f(&g_val3[b][tid][0]);
            float sw3 = ldcg_f(&g_val3[b][tid][1]);
            #pragma unroll
            for (int o = 4; o; o >>= 1) {
                sr  += __shfl_xor_sync(0xffu, sr,  o, 8);
                sw3 += __shfl_xor_sync(0xffu, sw3, o, 8);
            }
            if (tid == 0) { sh[S_SCR + 46] = sr; sh[S_SCR + 47] = sw3; }
        }
        __syncthreads();
        {
            const float inv_sr = 1.f / sh[S_SCR + 46];
            const float inv_sw = 1.f / sh[S_SCR + 47];
            sh[S_SWR + tid] = sh[S_WUR + tid] * inv_sr;
            sh[S_SWW + tid] = sh[S_WUW + tid] * inv_sw;
            __syncthreads();
            const float4* wr4 = (const float4*)(sh + S_SWR);
            const float4* ww4 = (const float4*)(sh + S_SWW);
            #pragma unroll
            for (int i = 0; i < 4; ++i) {
                const int w = warp*4 + i;
                const float e = P[140 + w], a = P[204 + w];
                float4* mp = (float4*)(sh + S_MEM + w*CHUNK);
                float racc = 0.f;
                #pragma unroll
                for (int j = lane; j < CHUNK/4; j += 32) {
                    float4 m = mp[j];
                    const float4 r = wr4[j];
                    const float4 q = ww4[j];
                    racc += m.x*r.x + m.y*r.y + m.z*r.z + m.w*r.w;   // OLD memory
                    m.x = m.x*(1.f - q.x*e) + q.x*a;
                    m.y = m.y*(1.f - q.y*e) + q.y*a;
                    m.z = m.z*(1.f - q.z*e) + q.z*a;
                    m.w = m.w*(1.f - q.w*e) + q.w*a;
                    mp[j] = m;
                }
                #pragma unroll
                for (int o = 16; o; o >>= 1) racc += __shfl_xor_sync(0xffffffffu, racc, o);
                if (lane == 0) sh[S_SCR + 64 + w] = racc;
            }
            __syncthreads();
            if (tid < 16) {
                const float4 v = *(const float4*)(sh + S_SCR + 64 + 4*tid);
                stcg_f4(&g_val4[b][chunk][16 + 4*tid], v);
                __threadfence();
            } else if (tid == 16) {
                stcg_f4(&g_val4[b][chunk][0],
                        make_float4(sh[S_SWR+0], sh[S_SWR+CHUNK-1],
                                    sh[S_SWW+0], sh[S_SWW+CHUNK-1]));
                __threadfence();
            }
            __syncthreads();
            if (tid == 0) stcg_u(&g_tick4[b][chunk], (unsigned)(t+1));
        }
    }
}

extern "C" void kernel_launch(void* const* d_in, const int* in_sizes, int n_in,
                              void* d_out, int out_size) {
    const float* x  = (const float*)d_in[0];   // (T,B,IN) fp32
    const float* Wc = (const float*)d_in[1];   // (192,332) fp32
    const float* bc = (const float*)d_in[2];   // (332,)   fp32
    static bool attr_done = false;
    if (!attr_done) {
        cudaFuncSetAttribute(ntm_kernel, cudaFuncAttributeMaxDynamicSharedMemorySize,
                             S_TOT * sizeof(float));
        attr_done = true;
    }
    ntm_kernel<<<NBLK, NTHR, S_TOT * sizeof(float)>>>(x, Wc, bc, (float*)d_out);
}

// round 8
// speedup vs baseline: 1.8964x; 1.0289x over previous
#include <cuda_runtime.h>
#include <cstdint>

#define TT   32
#define BB   16
#define INS  64
#define OUTS 64
#define LL   4096
#define WW   64
#define CO   332      // OUT + 70 + 198
#define NBLK 128
#define NTHR 512
#define CHUNK 512

// ---- smem layout (float offsets) ----
#define S_MEM 0        // 64*512 memory slice [w][l]
#define S_SWR 32768    // 512 normalized read w (w_prev)
#define S_SWW 33280    // 512 normalized write w
#define S_ER  33792    // 512 exp read   (init: x staging uses ER..WUW 2048)
#define S_EW  34304    // 512 exp write
#define S_WUR 34816    // 512 sharpened unnorm read
#define S_WUW 35328    // 512 sharpened unnorm write
#define S_SCR 35840    // 512 scratch
#define S_PAR 36352    // 288 params (+280/281: inv_sr_prev / inv_sw_prev)
#define S_OUT 36640    // 64  controller out (prev step)
#define S_COX 36704    // 32*332 = 10624 precomputed x@Wc + bc
#define S_TOT 47328    // floats -> 189312 bytes

// ---------------- persistent device state ----------------
__device__ float g_WcT[CO*192];                   // transposed controller weights
// val2: [0]=s_er [1]=s_ew [2]=er0 [3]=er511 [4]=ew0 [5]=ew511          (tick2)
// val3 (x2 buffers): [0]=s_wur [1]=s_wuw [2]=wur0 [3]=wur511 [4]=wuw0 [5]=wuw511 (tick3)
// val4: [16..79]=rpart[64] (UNNORMALIZED)                               (tick4)
__device__ __align__(128) float g_val2[BB][8][8];
__device__ __align__(128) float g_val3[2][BB][8][8];
__device__ __align__(128) float g_val4[BB][8][96];
__device__ __align__(128) unsigned g_tick2[BB][32];
__device__ __align__(128) unsigned g_tick3[BB][32];
__device__ __align__(128) unsigned g_tick4[BB][32];

__device__ __forceinline__ float softplusf(float x) {
    return (x > 20.f) ? x : log1pf(__expf(x));
}
__device__ __forceinline__ float sigmoidf(float x) {
    return 1.f / (1.f + __expf(-x));
}
__device__ __forceinline__ unsigned ldcg_u(const unsigned* p) {
    unsigned v; asm volatile("ld.global.cg.u32 %0, [%1];" : "=r"(v) : "l"(p)); return v;
}
__device__ __forceinline__ float ldcg_f(const float* p) {
    float v; asm volatile("ld.global.cg.f32 %0, [%1];" : "=f"(v) : "l"(p)); return v;
}
__device__ __forceinline__ void stcg_u(unsigned* p, unsigned v) {
    asm volatile("st.global.cg.u32 [%0], %1;" :: "l"(p), "r"(v) : "memory");
}
__device__ __forceinline__ void stcg_f(float* p, float v) {
    asm volatile("st.global.cg.f32 [%0], %1;" :: "l"(p), "f"(v) : "memory");
}
__device__ __forceinline__ void stcg_f4(float* p, float4 v) {
    asm volatile("st.global.cg.v4.f32 [%0], {%1,%2,%3,%4};"
                 :: "l"(p), "f"(v.x), "f"(v.y), "f"(v.z), "f"(v.w) : "memory");
}

// Poll 8 tickets for exact value `want` (lanes 0..7 of warp 0), then block-sync.
__device__ __forceinline__ void poll8(const unsigned* ticks, unsigned want, int tid) {
    if (tid < 8) {
        int n = 0;
        while (ldcg_u(&ticks[tid]) != want) { if (++n > 64) __nanosleep(32); }
    }
    __syncthreads();
}

__global__ __launch_bounds__(NTHR)
void ntm_kernel(const float* __restrict__ x, const float* __restrict__ Wc,
                const float* __restrict__ bc, float* __restrict__ dout)
{
    extern __shared__ __align__(16) float sh[];
    const int tid   = threadIdx.x;
    const int warp  = tid >> 5;
    const int lane  = tid & 31;
    const int b     = blockIdx.x >> 3;   // batch
    const int chunk = blockIdx.x & 7;
    const int l0    = chunk * CHUNK;

    // ================= init =================
    {
        float4* m4 = (float4*)(sh + S_MEM);
        for (int i = tid; i < WW*CHUNK/4; i += NTHR) m4[i] = make_float4(0,0,0,0);
        for (int k = tid; k < CHUNK; k += NTHR) {
            float v = (l0 + k == 0) ? 1.f : 0.f;
            sh[S_SWR + k] = v; sh[S_SWW + k] = v;
        }
        if (tid < 64) sh[S_OUT + tid] = 0.f;
        if (tid == 0) stcg_u(&g_tick2[b][chunk], 0u);   // replay-safe reset

        // WcT slice: rows i in [chunk*24, chunk*24+24)
        for (int idx = tid; idx < 24*CO; idx += NTHR) {
            const int i = chunk*24 + idx / CO;
            const int j = idx % CO;
            stcg_f(&g_WcT[j*192 + i], __ldg(&Wc[i*CO + j]));
        }
        __threadfence();
        __syncthreads();
        if (tid == 0) stcg_u(&g_tick3[b][chunk], 0u);   // WcT-done marker + reset
        poll8(g_tick3[b], 0u, tid);

        // stage x for this batch into ER..WUW scratch (2048 floats)
        for (int idx = tid; idx < TT*INS; idx += NTHR) {
            const int t = idx >> 6, i = idx & 63;
            sh[S_ER + idx] = __ldg(&x[(t*BB + b)*INS + i]);
        }
        __syncthreads();
        // coX[t][j] = bc[j] + x[t] @ WcT[j][0:64]
        if (tid < CO) {
            const float4* wp4 = (const float4*)(g_WcT + tid*192);
            const float bj = __ldg(&bc[tid]);
            #pragma unroll
            for (int th = 0; th < 4; th++) {
                float acc[8];
                #pragma unroll
                for (int k = 0; k < 8; k++) acc[k] = bj;
                #pragma unroll 4
                for (int q = 0; q < 16; q++) {
                    const float4 w = __ldg(wp4 + q);
                    #pragma unroll
                    for (int k = 0; k < 8; k++) {
                        const float* xr = sh + S_ER + (th*8 + k)*64 + q*4;
                        acc[k] = fmaf(w.x, xr[0], acc[k]);
                        acc[k] = fmaf(w.y, xr[1], acc[k]);
                        acc[k] = fmaf(w.z, xr[2], acc[k]);
                        acc[k] = fmaf(w.w, xr[3], acc[k]);
                    }
                }
                #pragma unroll
                for (int k = 0; k < 8; k++)
                    sh[S_COX + (th*8 + k)*CO + tid] = acc[k];
            }
        }
        // initial mailbox state (all stores 16B-aligned)
        if (tid < 16) {
            stcg_f4(&g_val4[b][chunk][16 + 4*tid], make_float4(0,0,0,0)); // rpart=0
            __threadfence();
        } else if (tid == 16) {
            // val3 buffer 1 (read at t=0): layout [0]=s_wur [1]=s_wuw
            // [2]=wur0 [3]=wur511 [4]=wuw0 [5]=wuw511 ; unnormalized initial w
            const float d0 = (l0 == 0) ? 1.f : 0.f;
            float* v3 = &g_val3[1][b][chunk][0];
            stcg_f4(v3,     make_float4(0.f, 0.f, d0, 0.f));   // [2]=wur0, [3]=wur511
            stcg_f4(v3 + 4, make_float4(d0, 0.f, 0.f, 0.f));   // [4]=wuw0, [5]=wuw511
            __threadfence();
        } else if (tid == 17) {
            sh[S_PAR + 280] = 1.f;   // inv_sr_prev
            sh[S_PAR + 281] = 1.f;   // inv_sw_prev
        }
        __syncthreads();
        if (tid == 0) stcg_u(&g_tick4[b][chunk], 0u);
    }

    for (int t = 0; t < TT; ++t) {
        // ===== Phase 1: poll rparts, r-sum, controller GEMM, params =====
        poll8(g_tick4[b], (unsigned)t, tid);
        if (tid < 64) {
            float s = 0.f;
            #pragma unroll
            for (int i = 0; i < 8; i++) s += ldcg_f(&g_val4[b][i][16 + tid]);
            sh[S_SCR + tid]      = sh[S_OUT + tid];            // out_{t-1}
            sh[S_SCR + 64 + tid] = s * sh[S_PAR + 280];        // r_{t-1} (normalized)
        }
        __syncthreads();
        if (tid < CO) {
            float acc0 = sh[S_COX + t*CO + tid], acc1 = 0.f;
            const float4* wp4  = (const float4*)(g_WcT + tid*192 + 64);
            const float4* cat4 = (const float4*)(sh + S_SCR);
            #pragma unroll 8
            for (int q = 0; q < 16; q++) {
                const float4 w0 = __ldg(wp4 + q);
                const float4 c0 = cat4[q];
                acc0 = fmaf(w0.x, c0.x, acc0); acc0 = fmaf(w0.y, c0.y, acc0);
                acc0 = fmaf(w0.z, c0.z, acc0); acc0 = fmaf(w0.w, c0.w, acc0);
                const float4 w1 = __ldg(wp4 + 16 + q);
                const float4 c1 = cat4[16 + q];
                acc1 = fmaf(w1.x, c1.x, acc1); acc1 = fmaf(w1.y, c1.y, acc1);
                acc1 = fmaf(w1.z, c1.z, acc1); acc1 = fmaf(w1.w, c1.w, acc1);
            }
            sh[S_SCR + 128 + tid] = acc0 + acc1;              // co
        }
        __syncthreads();
        float* co   = sh + S_SCR + 128;
        float* scal = sh + S_SCR + 464;
        if (warp == 0) {            // ||k_r||^2
            float p = co[64+lane]*co[64+lane] + co[96+lane]*co[96+lane];
            #pragma unroll
            for (int o = 16; o; o >>= 1) p += __shfl_xor_sync(0xffffffffu, p, o);
            if (lane == 0) scal[14] = p;
        } else if (warp == 1) {     // ||k_w||^2
            float p = co[134+lane]*co[134+lane] + co[166+lane]*co[166+lane];
            #pragma unroll
            for (int o = 16; o; o >>= 1) p += __shfl_xor_sync(0xffffffffu, p, o);
            if (lane == 0) scal[15] = p;
        }
        __syncthreads();
        float* P = sh + S_PAR;
        if (tid == 0) {
            float beta_r = softplusf(co[128]);
            float beta_w = softplusf(co[198]);
            scal[0] = beta_r * rsqrtf(scal[14] + 1e-14f);
            scal[1] = beta_w * rsqrtf(scal[15] + 1e-14f);
            P[128] = beta_r;
            P[129] = sigmoidf(co[129]);
            P[130] = softplusf(co[130]) + 1.f;
            float m = fmaxf(co[131], fmaxf(co[132], co[133]));
            float e0=__expf(co[131]-m), e1=__expf(co[132]-m), e2=__expf(co[133]-m);
            float inv = 1.f/(e0+e1+e2);
            P[131]=e0*inv; P[132]=e1*inv; P[133]=e2*inv;
            P[134] = beta_w;
            P[135] = sigmoidf(co[199]);
            P[136] = softplusf(co[200]) + 1.f;
            m = fmaxf(co[201], fmaxf(co[202], co[203]));
            e0=__expf(co[201]-m); e1=__expf(co[202]-m); e2=__expf(co[203]-m);
            inv = 1.f/(e0+e1+e2);
            P[137]=e0*inv; P[138]=e1*inv; P[139]=e2*inv;
        }
        __syncthreads();
        if (tid < 64) {
            P[tid]       = co[64 + tid]  * scal[0];   // k_r * beta/||k_r||
            P[64 + tid]  = co[134 + tid] * scal[1];   // k_w * beta/||k_w||
            P[140 + tid] = sigmoidf(co[204 + tid]);   // e
            P[204 + tid] = co[268 + tid];             // a
            const float o = co[tid];
            sh[S_OUT + tid] = o;
            if (chunk == 0) dout[(t*BB + b)*OUTS + tid] = o;
        }
        __syncthreads();

        // ===== Phase 2: cosine similarity (smem, reduction-free) =====
        {
            const float beta_r = P[128], beta_w = P[134];
            const int l = tid;
            float dr = 0.f, dw = 0.f, ds = 0.f;
            #pragma unroll 16
            for (int w = 0; w < WW; ++w) {
                const float m = sh[S_MEM + w*CHUNK + l];
                dr = fmaf(m, P[w],      dr);
                dw = fmaf(m, P[64 + w], dw);
                ds = fmaf(m, m,         ds);
            }
            const float inm = rsqrtf(ds + 1e-14f);
            const float er = __expf(dr*inm - beta_r);   // arg in [-2b, 0]
            const float ew = __expf(dw*inm - beta_w);
            sh[S_ER + l] = er; sh[S_EW + l] = ew;
            float se = er, swv = ew;
            #pragma unroll
            for (int o = 16; o; o >>= 1) {
                se  += __shfl_xor_sync(0xffffffffu, se, o);
                swv += __shfl_xor_sync(0xffffffffu, swv, o);
            }
            if (lane == 0) { sh[S_SCR + warp] = se; sh[S_SCR + 16 + warp] = swv; }
            __syncthreads();
            if (tid == 0) {
                float a = 0.f, c = 0.f;
                #pragma unroll
                for (int i = 0; i < 16; ++i) { a += sh[S_SCR+i]; c += sh[S_SCR+16+i]; }
                stcg_f4(&g_val2[b][chunk][0],
                        make_float4(a, c, sh[S_ER+0], sh[S_ER+CHUNK-1]));
                stcg_f4(&g_val2[b][chunk][4],
                        make_float4(sh[S_EW+0], sh[S_EW+CHUNK-1], 0.f, 0.f));
                __threadfence();
                stcg_u(&g_tick2[b][chunk], (unsigned)(t+1));
            }
        }

        // ===== Phase 3: gate + shift + sharpen; post sums+halos EARLY =====
        poll8(g_tick2[b], (unsigned)(t+1), tid);
        if (tid < 8) {
            float se  = ldcg_f(&g_val2[b][tid][0]);
            float sw2 = ldcg_f(&g_val2[b][tid][1]);
            #pragma unroll
            for (int o = 4; o; o >>= 1) {
                se  += __shfl_xor_sync(0xffu, se,  o, 8);
                sw2 += __shfl_xor_sync(0xffu, sw2, o, 8);
            }
            if (tid == 0) { sh[S_SCR + 40] = se; sh[S_SCR + 41] = sw2; }
        }
        __syncthreads();
        {
            const float inv_ser = 1.f / sh[S_SCR + 40];
            const float inv_sew = 1.f / sh[S_SCR + 41];
            const float inv_srp = sh[S_PAR + 280];   // prev-step normalizers
            const float inv_swp = sh[S_PAR + 281];
            const float gr  = P[129], gamr = P[130];
            const float sr0 = P[131], sr1 = P[132], sr2 = P[133];
            const float gw  = P[135], gamw = P[136];
            const float sw0 = P[137], sw1 = P[138], sw2 = P[139];
            const int prv = (chunk + 7) & 7, nxt = (chunk + 1) & 7;
            const int pb  = (t & 1) ^ 1;             // val3 buffer of step t-1
            const int k = tid;
            float cmr, cmw, pmr, pmw, cpr, cpw, ppr, ppw;
            if (k == 0) {
                cmr = ldcg_f(&g_val2[b][prv][3]); cmw = ldcg_f(&g_val2[b][prv][5]);
                pmr = ldcg_f(&g_val3[pb][b][prv][3]) * inv_srp;
                pmw = ldcg_f(&g_val3[pb][b][prv][5]) * inv_swp;
            } else {
                cmr = sh[S_ER + k-1];  cmw = sh[S_EW + k-1];
                pmr = sh[S_SWR + k-1]; pmw = sh[S_SWW + k-1];
            }
            if (k == CHUNK-1) {
                cpr = ldcg_f(&g_val2[b][nxt][2]); cpw = ldcg_f(&g_val2[b][nxt][4]);
                ppr = ldcg_f(&g_val3[pb][b][nxt][2]) * inv_srp;
                ppw = ldcg_f(&g_val3[pb][b][nxt][4]) * inv_swp;
            } else {
                cpr = sh[S_ER + k+1];  cpw = sh[S_EW + k+1];
                ppr = sh[S_SWR + k+1]; ppw = sh[S_SWW + k+1];
            }
            const float ccr = sh[S_ER + k],  pcr = sh[S_SWR + k];
            const float ccw = sh[S_EW + k],  pcw = sh[S_SWW + k];
            float wgm = cmr*inv_ser*gr + (1.f-gr)*pmr;
            float wgc = ccr*inv_ser*gr + (1.f-gr)*pcr;
            float wgp = cpr*inv_ser*gr + (1.f-gr)*ppr;
            const float wur = powf(fmaxf(sr0*wgm + sr1*wgc + sr2*wgp, 0.f), gamr);
            wgm = cmw*inv_sew*gw + (1.f-gw)*pmw;
            wgc = ccw*inv_sew*gw + (1.f-gw)*pcw;
            wgp = cpw*inv_sew*gw + (1.f-gw)*ppw;
            const float wuw = powf(fmaxf(sw0*wgm + sw1*wgc + sw2*wgp, 0.f), gamw);
            sh[S_WUR + k] = wur; sh[S_WUW + k] = wuw;
            float ps_r = wur, ps_w = wuw;
            #pragma unroll
            for (int o = 16; o; o >>= 1) {
                ps_r += __shfl_xor_sync(0xffffffffu, ps_r, o);
                ps_w += __shfl_xor_sync(0xffffffffu, ps_w, o);
            }
            if (lane == 0) { sh[S_SCR + warp] = ps_r; sh[S_SCR + 16 + warp] = ps_w; }
            __syncthreads();
            if (tid == 0) {
                float a = 0.f, c = 0.f;
                #pragma unroll
                for (int i = 0; i < 16; ++i) { a += sh[S_SCR+i]; c += sh[S_SCR+16+i]; }
                float* v3 = &g_val3[t & 1][b][chunk][0];
                stcg_f4(v3,     make_float4(a, c, sh[S_WUR+0], sh[S_WUR+CHUNK-1]));
                stcg_f4(v3 + 4, make_float4(sh[S_WUW+0], sh[S_WUW+CHUNK-1], 0.f, 0.f));
                __threadfence();
                stcg_u(&g_tick3[b][chunk], (unsigned)(t+1));
            }
        }

        // ===== Phase 4a: UNNORMALIZED r-partials, post tick4 (hides tick3) =====
        {
            const float4* wur4 = (const float4*)(sh + S_WUR);
            #pragma unroll
            for (int i = 0; i < 4; ++i) {
                const int w = warp*4 + i;
                const float4* mp = (const float4*)(sh + S_MEM + w*CHUNK);
                float racc = 0.f;
                #pragma unroll
                for (int j = lane; j < CHUNK/4; j += 32) {
                    const float4 m = mp[j];
                    const float4 r = wur4[j];
                    racc += m.x*r.x + m.y*r.y + m.z*r.z + m.w*r.w;
                }
                #pragma unroll
                for (int o = 16; o; o >>= 1) racc += __shfl_xor_sync(0xffffffffu, racc, o);
                if (lane == 0) sh[S_SCR + 64 + w] = racc;
            }
            __syncthreads();
            if (tid < 16) {
                const float4 v = *(const float4*)(sh + S_SCR + 64 + 4*tid);
                stcg_f4(&g_val4[b][chunk][16 + 4*tid], v);
                __threadfence();
            }
            __syncthreads();
            if (tid == 0) stcg_u(&g_tick4[b][chunk], (unsigned)(t+1));
        }

        // ===== Phase 4b: poll tick3 (likely ready), normalize, mem update =====
        poll8(g_tick3[b], (unsigned)(t+1), tid);
        if (tid < 8) {
            float sr  = ldcg_f(&g_val3[t & 1][b][tid][0]);
            float sw3 = ldcg_f(&g_val3[t & 1][b][tid][1]);
            #pragma unroll
            for (int o = 4; o; o >>= 1) {
                sr  += __shfl_xor_sync(0xffu, sr,  o, 8);
                sw3 += __shfl_xor_sync(0xffu, sw3, o, 8);
            }
            if (tid == 0) {
                sh[S_PAR + 280] = 1.f / sr;    // inv_sr (used next step)
                sh[S_PAR + 281] = 1.f / sw3;   // inv_sw
            }
        }
        __syncthreads();
        {
            const float inv_sr = sh[S_PAR + 280];
            const float inv_sw = sh[S_PAR + 281];
            sh[S_SWR + tid] = sh[S_WUR + tid] * inv_sr;   // w_prev for next step
            sh[S_SWW + tid] = sh[S_WUW + tid] * inv_sw;
            __syncthreads();
            const float4* ww4 = (const float4*)(sh + S_SWW);
            #pragma unroll
            for (int i = 0; i < 4; ++i) {
                const int w = warp*4 + i;
                const float e = P[140 + w], a = P[204 + w];
                float4* mp = (float4*)(sh + S_MEM + w*CHUNK);
                #pragma unroll
                for (int j = lane; j < CHUNK/4; j += 32) {
                    float4 m = mp[j];
                    const float4 q = ww4[j];
                    m.x = m.x*(1.f - q.x*e) + q.x*a;
                    m.y = m.y*(1.f - q.y*e) + q.y*a;
                    m.z = m.z*(1.f - q.z*e) + q.z*a;
                    m.w = m.w*(1.f - q.w*e) + q.w*a;
                    mp[j] = m;
                }
            }
            __syncthreads();
        }
    }
}

extern "C" void kernel_launch(void* const* d_in, const int* in_sizes, int n_in,
                              void* d_out, int out_size) {
    const float* x  = (const float*)d_in[0];   // (T,B,IN) fp32
    const float* Wc = (const float*)d_in[1];   // (192,332) fp32
    const float* bc = (const float*)d_in[2];   // (332,)   fp32
    static bool attr_done = false;
    if (!attr_done) {
        cudaFuncSetAttribute(ntm_kernel, cudaFuncAttributeMaxDynamicSharedMemorySize,
                             S_TOT * sizeof(float));
        attr_done = true;
    }
    ntm_kernel<<<NBLK, NTHR, S_TOT * sizeof(float)>>>(x, Wc, bc, (float*)d_out);
}

// round 9
// speedup vs baseline: 2.0229x; 1.0667x over previous
#include <cuda_runtime.h>
#include <cstdint>

#define TT   32
#define BB   16
#define INS  64
#define OUTS 64
#define LL   4096
#define WW   64
#define CO   332      // OUT + 70 + 198
#define NBLK 128
#define NTHR 512
#define CHUNK 512
#define PERJ 42       // co outputs per block (last block: 38)

// ---- smem layout (float offsets) ----
#define S_MEM  0        // 64*512 memory slice [w][l]
#define S_SWR  32768    // 512 normalized read w_prev
#define S_SWW  33280    // 512 normalized write w_prev
#define S_WWN  33792    // 512 PENDING normalized write weight (lazy update)
#define S_EAP  34304    // 128 pending packed (e,a) per w
#define S_KEY  34432    // 128 packed (kr,kw) per w
#define S_ER   34560    // 512 exp read    (init: x staging uses ER..WUW 2048)
#define S_EW   35072    // 512 exp write
#define S_WUR  35584    // 512 sharpened unnorm read
#define S_WUW  36096    // 512 sharpened unnorm write
#define S_SCR  36608    // 512 scratch: cat(128)+co(332)+scal(16); reductions
#define S_PAR  37120    // 288 params (+280/281: inv_sr_prev / inv_sw_prev)
#define S_COX  37408    // 32*42 = 1344 x@Wc slice for OWN j's
#define S_COSH 38752    // 48  co slice staging
#define S_TOT  38800    // floats -> 155200 bytes

// ---------------- persistent device state ----------------
__device__ float g_WcT[CO*192];                   // transposed controller weights
// val1: co exchange, 48 floats/slot, double-buffered by t&1       (tick1)
// val2: [0]=s_er [1]=s_ew [2]=er0 [3]=er511 [4]=ew0 [5]=ew511     (tick2)
// val3 x2: [0]=s_wur [1]=s_wuw [2]=wur0 [3]=wur511 [4]=wuw0 [5]=wuw511 (tick3)
// val4: [16..79]=rpart[64] (UNNORMALIZED)                          (tick4)
__device__ __align__(128) float g_val1[2][BB][8][48];
__device__ __align__(128) float g_val2[BB][8][8];
__device__ __align__(128) float g_val3[2][BB][8][8];
__device__ __align__(128) float g_val4[BB][8][96];
__device__ __align__(128) unsigned g_tick1[BB][32];
__device__ __align__(128) unsigned g_tick2[BB][32];
__device__ __align__(128) unsigned g_tick3[BB][32];
__device__ __align__(128) unsigned g_tick4[BB][32];

__device__ __forceinline__ float softplusf(float x) {
    return (x > 20.f) ? x : log1pf(__expf(x));
}
__device__ __forceinline__ float sigmoidf(float x) {
    return 1.f / (1.f + __expf(-x));
}
__device__ __forceinline__ unsigned ldcg_u(const unsigned* p) {
    unsigned v; asm volatile("ld.global.cg.u32 %0, [%1];" : "=r"(v) : "l"(p)); return v;
}
__device__ __forceinline__ float ldcg_f(const float* p) {
    float v; asm volatile("ld.global.cg.f32 %0, [%1];" : "=f"(v) : "l"(p)); return v;
}
__device__ __forceinline__ void stcg_u(unsigned* p, unsigned v) {
    asm volatile("st.global.cg.u32 [%0], %1;" :: "l"(p), "r"(v) : "memory");
}
__device__ __forceinline__ void stcg_f(float* p, float v) {
    asm volatile("st.global.cg.f32 [%0], %1;" :: "l"(p), "f"(v) : "memory");
}
__device__ __forceinline__ void stcg_f4(float* p, float4 v) {
    asm volatile("st.global.cg.v4.f32 [%0], {%1,%2,%3,%4};"
                 :: "l"(p), "f"(v.x), "f"(v.y), "f"(v.z), "f"(v.w) : "memory");
}

// Poll 8 tickets for exact value `want` (lanes 0..7 of warp 0), then block-sync.
__device__ __forceinline__ void poll8(const unsigned* ticks, unsigned want, int tid) {
    if (tid < 8) {
        int n = 0;
        while (ldcg_u(&ticks[tid]) != want) { if (++n > 64) __nanosleep(32); }
    }
    __syncthreads();
}

__global__ __launch_bounds__(NTHR)
void ntm_kernel(const float* __restrict__ x, const float* __restrict__ Wc,
                const float* __restrict__ bc, float* __restrict__ dout)
{
    extern __shared__ __align__(16) float sh[];
    const int tid   = threadIdx.x;
    const int warp  = tid >> 5;
    const int lane  = tid & 31;
    const int b     = blockIdx.x >> 3;   // batch
    const int chunk = blockIdx.x & 7;
    const int l0    = chunk * CHUNK;
    const int nj    = (chunk == 7) ? 38 : PERJ;
    const int jbase = chunk * PERJ;
    float* P = sh + S_PAR;

    // ================= init =================
    {
        float4* m4 = (float4*)(sh + S_MEM);
        for (int i = tid; i < WW*CHUNK/4; i += NTHR) m4[i] = make_float4(0,0,0,0);
        for (int k = tid; k < CHUNK; k += NTHR) {
            float v = (l0 + k == 0) ? 1.f : 0.f;
            sh[S_SWR + k] = v; sh[S_SWW + k] = v;
            sh[S_WWN + k] = 0.f;                     // no pending update at t=0
        }
        if (tid < 128) sh[S_EAP + tid] = 0.f;
        if (tid == 0) {                              // replay-safe resets
            stcg_u(&g_tick1[b][chunk], 0u);
            stcg_u(&g_tick2[b][chunk], 0u);
        }

        // WcT slice: rows i in [chunk*24, chunk*24+24)
        for (int idx = tid; idx < 24*CO; idx += NTHR) {
            const int i = chunk*24 + idx / CO;
            const int j = idx % CO;
            stcg_f(&g_WcT[j*192 + i], __ldg(&Wc[i*CO + j]));
        }
        __threadfence();
        __syncthreads();
        if (tid == 0) stcg_u(&g_tick3[b][chunk], 0u);   // WcT-done marker + reset
        poll8(g_tick3[b], 0u, tid);

        // stage x for this batch into ER..WUW scratch (2048 floats)
        for (int idx = tid; idx < TT*INS; idx += NTHR) {
            const int t = idx >> 6, i = idx & 63;
            sh[S_ER + idx] = __ldg(&x[(t*BB + b)*INS + i]);
        }
        __syncthreads();
        // coX[t][jl] = bc[j] + x[t] @ Wc[0:64, j]   (own j-slice only)
        // thread = jl*8 + tg ; tg covers 4 timesteps
        if (tid < PERJ*8) {
            const int jl = tid >> 3, tg = tid & 7;
            if (jl < nj) {
                const int j = jbase + jl;
                const float bj = __ldg(&bc[j]);
                float acc[4];
                #pragma unroll
                for (int k = 0; k < 4; ++k) acc[k] = bj;
                for (int i = 0; i < INS; ++i) {
                    const float w = __ldg(&Wc[i*CO + j]);
                    #pragma unroll
                    for (int k = 0; k < 4; ++k)
                        acc[k] = fmaf(sh[S_ER + (tg*4 + k)*64 + i], w, acc[k]);
                }
                #pragma unroll
                for (int k = 0; k < 4; ++k)
                    sh[S_COX + (tg*4 + k)*PERJ + jl] = acc[k];
            }
        }
        __syncthreads();
        // initial mailbox state (all stores 16B-aligned)
        if (tid < 16) {
            stcg_f4(&g_val4[b][chunk][16 + 4*tid], make_float4(0,0,0,0)); // rpart=0
            __threadfence();
        } else if (tid < 28) {
            stcg_f4(&g_val1[1][b][chunk][4*(tid-16)], make_float4(0,0,0,0)); // out0=0
            __threadfence();
        } else if (tid == 28) {
            // val3 buffer 1: [2]=wur0 [3]=wur511 [4]=wuw0 [5]=wuw511, unnorm init w
            const float d0 = (l0 == 0) ? 1.f : 0.f;
            float* v3 = &g_val3[1][b][chunk][0];
            stcg_f4(v3,     make_float4(0.f, 0.f, d0, 0.f));
            stcg_f4(v3 + 4, make_float4(d0, 0.f, 0.f, 0.f));
            __threadfence();
        } else if (tid == 29) {
            sh[S_PAR + 280] = 1.f;   // inv_sr_prev
            sh[S_PAR + 281] = 1.f;   // inv_sw_prev
        }
        __syncthreads();
        if (tid == 0) stcg_u(&g_tick4[b][chunk], 0u);
    }

    for (int t = 0; t < TT; ++t) {
        // ===== Phase 1: cat build, distributed GEMM, co exchange, params ====
        poll8(g_tick4[b], (unsigned)t, tid);
        if (tid < 64) {                              // out_{t-1} from co mailbox
            const int jb = tid / PERJ, jl = tid - jb*PERJ;
            sh[S_SCR + tid] = ldcg_f(&g_val1[(t+1)&1][b][jb][jl]);
        } else if (tid < 128) {                      // r_{t-1} = rparts * inv_sr
            float s = 0.f;
            #pragma unroll
            for (int i = 0; i < 8; i++) s += ldcg_f(&g_val4[b][i][16 + tid - 64]);
            sh[S_SCR + tid] = s * sh[S_PAR + 280];
        }
        __syncthreads();
        {   // GEMM slice: 4 threads per output j; all threads shfl (clamped j)
            const int jl = tid >> 2, q = tid & 3;
            const int jc = (jl < nj) ? jl : nj - 1;
            const float4* wp = (const float4*)(g_WcT + (jbase + jc)*192 + 64 + q*32);
            const float4* cp = (const float4*)(sh + S_SCR + q*32);
            float acc = 0.f;
            #pragma unroll
            for (int i = 0; i < 8; ++i) {
                const float4 w = __ldg(wp + i);
                const float4 c = cp[i];
                acc = fmaf(w.x, c.x, acc); acc = fmaf(w.y, c.y, acc);
                acc = fmaf(w.z, c.z, acc); acc = fmaf(w.w, c.w, acc);
            }
            acc += __shfl_xor_sync(0xffffffffu, acc, 1);
            acc += __shfl_xor_sync(0xffffffffu, acc, 2);
            if (q == 0 && jl < nj)
                sh[S_COSH + jl] = acc + sh[S_COX + t*PERJ + jl];
        }
        __syncthreads();
        if (tid < 12) {
            const float4 v = *(const float4*)(sh + S_COSH + 4*tid);
            stcg_f4(&g_val1[t&1][b][chunk][4*tid], v);
            __threadfence();
        }
        __syncthreads();
        if (tid == 0) stcg_u(&g_tick1[b][chunk], (unsigned)(t+1));
        poll8(g_tick1[b], (unsigned)(t+1), tid);
        if (tid < CO) {                              // assemble full co
            const int jb = tid / PERJ, jl = tid - jb*PERJ;
            sh[S_SCR + 128 + tid] = ldcg_f(&g_val1[t&1][b][jb][jl]);
        }
        __syncthreads();
        float* co   = sh + S_SCR + 128;
        float* scal = sh + S_SCR + 464;
        if (warp == 0) {            // ||k_r||^2
            float p = co[64+lane]*co[64+lane] + co[96+lane]*co[96+lane];
            #pragma unroll
            for (int o = 16; o; o >>= 1) p += __shfl_xor_sync(0xffffffffu, p, o);
            if (lane == 0) scal[14] = p;
        } else if (warp == 1) {     // ||k_w||^2
            float p = co[134+lane]*co[134+lane] + co[166+lane]*co[166+lane];
            #pragma unroll
            for (int o = 16; o; o >>= 1) p += __shfl_xor_sync(0xffffffffu, p, o);
            if (lane == 0) scal[15] = p;
        }
        __syncthreads();
        if (tid == 0) {
            float beta_r = softplusf(co[128]);
            float beta_w = softplusf(co[198]);
            scal[0] = beta_r * rsqrtf(scal[14] + 1e-14f);
            scal[1] = beta_w * rsqrtf(scal[15] + 1e-14f);
            P[128] = beta_r;
            P[129] = sigmoidf(co[129]);
            P[130] = softplusf(co[130]) + 1.f;
            float m = fmaxf(co[131], fmaxf(co[132], co[133]));
            float e0=__expf(co[131]-m), e1=__expf(co[132]-m), e2=__expf(co[133]-m);
            float inv = 1.f/(e0+e1+e2);
            P[131]=e0*inv; P[132]=e1*inv; P[133]=e2*inv;
            P[134] = beta_w;
            P[135] = sigmoidf(co[199]);
            P[136] = softplusf(co[200]) + 1.f;
            m = fmaxf(co[201], fmaxf(co[202], co[203]));
            e0=__expf(co[201]-m); e1=__expf(co[202]-m); e2=__expf(co[203]-m);
            inv = 1.f/(e0+e1+e2);
            P[137]=e0*inv; P[138]=e1*inv; P[139]=e2*inv;
        }
        __syncthreads();
        if (tid < 64) {
            const float kr = co[64 + tid]  * scal[0];
            const float kw = co[134 + tid] * scal[1];
            sh[S_KEY + 2*tid]     = kr;               // packed keys
            sh[S_KEY + 2*tid + 1] = kw;
            P[140 + tid] = sigmoidf(co[204 + tid]);   // e
            P[204 + tid] = co[268 + tid];             // a
            if (chunk == 0) dout[(t*BB + b)*OUTS + tid] = co[tid];
        }
        __syncthreads();

        // ===== Phase 2 (fused): apply pending update + cosine sim ==========
        if (tid < 128) {
            const float beta_r = P[128], beta_w = P[134];
            const float4 wn = *(const float4*)(sh + S_WWN + 4*tid);
            float4 dr = make_float4(0,0,0,0), dw = dr, ds = dr;
            #pragma unroll 8
            for (int w = 0; w < WW; ++w) {
                float4* mp = (float4*)(sh + S_MEM + w*CHUNK + 4*tid);
                float4 m = *mp;
                const float2 ea = *(const float2*)(sh + S_EAP + 2*w);
                m.x = m.x*(1.f - wn.x*ea.x) + wn.x*ea.y;   // lazy update (t-1)
                m.y = m.y*(1.f - wn.y*ea.x) + wn.y*ea.y;
                m.z = m.z*(1.f - wn.z*ea.x) + wn.z*ea.y;
                m.w = m.w*(1.f - wn.w*ea.x) + wn.w*ea.y;
                *mp = m;
                const float2 k = *(const float2*)(sh + S_KEY + 2*w);
                dr.x = fmaf(m.x,k.x,dr.x); dr.y = fmaf(m.y,k.x,dr.y);
                dr.z = fmaf(m.z,k.x,dr.z); dr.w = fmaf(m.w,k.x,dr.w);
                dw.x = fmaf(m.x,k.y,dw.x); dw.y = fmaf(m.y,k.y,dw.y);
                dw.z = fmaf(m.z,k.y,dw.z); dw.w = fmaf(m.w,k.y,dw.w);
                ds.x = fmaf(m.x,m.x,ds.x); ds.y = fmaf(m.y,m.y,ds.y);
                ds.z = fmaf(m.z,m.z,ds.z); ds.w = fmaf(m.w,m.w,ds.w);
            }
            float4 er, ew;
            {
                const float i0 = rsqrtf(ds.x + 1e-14f), i1 = rsqrtf(ds.y + 1e-14f);
                const float i2 = rsqrtf(ds.z + 1e-14f), i3 = rsqrtf(ds.w + 1e-14f);
                er.x = __expf(dr.x*i0 - beta_r); er.y = __expf(dr.y*i1 - beta_r);
                er.z = __expf(dr.z*i2 - beta_r); er.w = __expf(dr.w*i3 - beta_r);
                ew.x = __expf(dw.x*i0 - beta_w); ew.y = __expf(dw.y*i1 - beta_w);
                ew.z = __expf(dw.z*i2 - beta_w); ew.w = __expf(dw.w*i3 - beta_w);
            }
            *(float4*)(sh + S_ER + 4*tid) = er;
            *(float4*)(sh + S_EW + 4*tid) = ew;
            float se = er.x + er.y + er.z + er.w;
            float sw = ew.x + ew.y + ew.z + ew.w;
            #pragma unroll
            for (int o = 16; o; o >>= 1) {
                se += __shfl_xor_sync(0xffffffffu, se, o);
                sw += __shfl_xor_sync(0xffffffffu, sw, o);
            }
            if (lane == 0) { sh[S_SCR + warp] = se; sh[S_SCR + 16 + warp] = sw; }
        }
        __syncthreads();
        if (tid == 0) {
            float a = 0.f, c = 0.f;
            #pragma unroll
            for (int i = 0; i < 4; ++i) { a += sh[S_SCR+i]; c += sh[S_SCR+16+i]; }
            stcg_f4(&g_val2[b][chunk][0],
                    make_float4(a, c, sh[S_ER+0], sh[S_ER+CHUNK-1]));
            stcg_f4(&g_val2[b][chunk][4],
                    make_float4(sh[S_EW+0], sh[S_EW+CHUNK-1], 0.f, 0.f));
            __threadfence();
            stcg_u(&g_tick2[b][chunk], (unsigned)(t+1));
        }

        // ===== Phase 3: gate + shift + sharpen; post wu sums+halos ==========
        poll8(g_tick2[b], (unsigned)(t+1), tid);
        if (tid < 8) {
            float se  = ldcg_f(&g_val2[b][tid][0]);
            float sw2 = ldcg_f(&g_val2[b][tid][1]);
            #pragma unroll
            for (int o = 4; o; o >>= 1) {
                se  += __shfl_xor_sync(0xffu, se,  o, 8);
                sw2 += __shfl_xor_sync(0xffu, sw2, o, 8);
            }
            if (tid == 0) { sh[S_SCR + 40] = se; sh[S_SCR + 41] = sw2; }
        }
        __syncthreads();
        {
            const float inv_ser = 1.f / sh[S_SCR + 40];
            const float inv_sew = 1.f / sh[S_SCR + 41];
            const float inv_srp = sh[S_PAR + 280];
            const float inv_swp = sh[S_PAR + 281];
            const float gr  = P[129], gamr = P[130];
            const float sr0 = P[131], sr1 = P[132], sr2 = P[133];
            const float gw  = P[135], gamw = P[136];
            const float sw0 = P[137], sw1 = P[138], sw2 = P[139];
            const int prv = (chunk + 7) & 7, nxt = (chunk + 1) & 7;
            const int pb  = (t & 1) ^ 1;
            const int k = tid;
            float cmr, cmw, pmr, pmw, cpr, cpw, ppr, ppw;
            if (k == 0) {
                cmr = ldcg_f(&g_val2[b][prv][3]); cmw = ldcg_f(&g_val2[b][prv][5]);
                pmr = ldcg_f(&g_val3[pb][b][prv][3]) * inv_srp;
                pmw = ldcg_f(&g_val3[pb][b][prv][5]) * inv_swp;
            } else {
                cmr = sh[S_ER + k-1];  cmw = sh[S_EW + k-1];
                pmr = sh[S_SWR + k-1]; pmw = sh[S_SWW + k-1];
            }
            if (k == CHUNK-1) {
                cpr = ldcg_f(&g_val2[b][nxt][2]); cpw = ldcg_f(&g_val2[b][nxt][4]);
                ppr = ldcg_f(&g_val3[pb][b][nxt][2]) * inv_srp;
                ppw = ldcg_f(&g_val3[pb][b][nxt][4]) * inv_swp;
            } else {
                cpr = sh[S_ER + k+1];  cpw = sh[S_EW + k+1];
                ppr = sh[S_SWR + k+1]; ppw = sh[S_SWW + k+1];
            }
            const float ccr = sh[S_ER + k],  pcr = sh[S_SWR + k];
            const float ccw = sh[S_EW + k],  pcw = sh[S_SWW + k];
            float wgm = cmr*inv_ser*gr + (1.f-gr)*pmr;
            float wgc = ccr*inv_ser*gr + (1.f-gr)*pcr;
            float wgp = cpr*inv_ser*gr + (1.f-gr)*ppr;
            const float wur = powf(fmaxf(sr0*wgm + sr1*wgc + sr2*wgp, 0.f), gamr);
            wgm = cmw*inv_sew*gw + (1.f-gw)*pmw;
            wgc = ccw*inv_sew*gw + (1.f-gw)*pcw;
            wgp = cpw*inv_sew*gw + (1.f-gw)*ppw;
            const float wuw = powf(fmaxf(sw0*wgm + sw1*wgc + sw2*wgp, 0.f), gamw);
            sh[S_WUR + k] = wur; sh[S_WUW + k] = wuw;
            float ps_r = wur, ps_w = wuw;
            #pragma unroll
            for (int o = 16; o; o >>= 1) {
                ps_r += __shfl_xor_sync(0xffffffffu, ps_r, o);
                ps_w += __shfl_xor_sync(0xffffffffu, ps_w, o);
            }
            if (lane == 0) { sh[S_SCR + warp] = ps_r; sh[S_SCR + 16 + warp] = ps_w; }
            __syncthreads();
            if (tid == 0) {
                float a = 0.f, c = 0.f;
                #pragma unroll
                for (int i = 0; i < 16; ++i) { a += sh[S_SCR+i]; c += sh[S_SCR+16+i]; }
                float* v3 = &g_val3[t & 1][b][chunk][0];
                stcg_f4(v3,     make_float4(a, c, sh[S_WUR+0], sh[S_WUR+CHUNK-1]));
                stcg_f4(v3 + 4, make_float4(sh[S_WUW+0], sh[S_WUW+CHUNK-1], 0.f, 0.f));
                __threadfence();
                stcg_u(&g_tick3[b][chunk], (unsigned)(t+1));
            }
        }

        // ===== Phase 4a: UNNORMALIZED r-partials (old mem), post tick4 ======
        {
            float racc[4] = {0.f, 0.f, 0.f, 0.f};
            const int wbase = warp * 4;
            #pragma unroll
            for (int kk = 0; kk < 4; ++kk) {
                const int j = lane + 32*kk;
                const float4 r = *(const float4*)(sh + S_WUR + 4*j);
                #pragma unroll
                for (int w = 0; w < 4; ++w) {
                    const float4 m = *(const float4*)(sh + S_MEM + (wbase+w)*CHUNK + 4*j);
                    racc[w] += m.x*r.x + m.y*r.y + m.z*r.z + m.w*r.w;
                }
            }
            #pragma unroll
            for (int w = 0; w < 4; ++w) {
                #pragma unroll
                for (int o = 16; o; o >>= 1)
                    racc[w] += __shfl_xor_sync(0xffffffffu, racc[w], o);
                if (lane == 0) sh[S_SCR + 64 + wbase + w] = racc[w];
            }
        }
        __syncthreads();
        if (tid < 16) {
            const float4 v = *(const float4*)(sh + S_SCR + 64 + 4*tid);
            stcg_f4(&g_val4[b][chunk][16 + 4*tid], v);
            __threadfence();
        }
        __syncthreads();
        if (tid == 0) stcg_u(&g_tick4[b][chunk], (unsigned)(t+1));

        // ===== Normalize: poll wu sums, set pending update + w_prev =========
        poll8(g_tick3[b], (unsigned)(t+1), tid);
        if (tid < 8) {
            float sr  = ldcg_f(&g_val3[t & 1][b][tid][0]);
            float sw3 = ldcg_f(&g_val3[t & 1][b][tid][1]);
            #pragma unroll
            for (int o = 4; o; o >>= 1) {
                sr  += __shfl_xor_sync(0xffu, sr,  o, 8);
                sw3 += __shfl_xor_sync(0xffu, sw3, o, 8);
            }
            if (tid == 0) {
                sh[S_PAR + 280] = 1.f / sr;
                sh[S_PAR + 281] = 1.f / sw3;
            }
        }
        __syncthreads();
        {
            const float inv_sr = sh[S_PAR + 280];
            const float inv_sw = sh[S_PAR + 281];
            const float wn = sh[S_WUW + tid] * inv_sw;
            sh[S_SWR + tid] = sh[S_WUR + tid] * inv_sr;   // w_prev (read head)
            sh[S_SWW + tid] = wn;                          // w_prev (write head)
            sh[S_WWN + tid] = wn;                          // pending update weight
            if (tid < 64) {                                // pending e,a (from P of t)
                sh[S_EAP + 2*tid]     = P[140 + tid];
                sh[S_EAP + 2*tid + 1] = P[204 + tid];
            }
        }
        __syncthreads();
    }
}

extern "C" void kernel_launch(void* const* d_in, const int* in_sizes, int n_in,
                              void* d_out, int out_size) {
    const float* x  = (const float*)d_in[0];   // (T,B,IN) fp32
    const float* Wc = (const float*)d_in[1];   // (192,332) fp32
    const float* bc = (const float*)d_in[2];   // (332,)   fp32
    static bool attr_done = false;
    if (!attr_done) {
        cudaFuncSetAttribute(ntm_kernel, cudaFuncAttributeMaxDynamicSharedMemorySize,
                             S_TOT * sizeof(float));
        attr_done = true;
    }
    ntm_kernel<<<NBLK, NTHR, S_TOT * sizeof(float)>>>(x, Wc, bc, (float*)d_out);
}